// round 16
// baseline (speedup 1.0000x reference)
#include <cuda_runtime.h>
#include <cstdint>

// ============================================================================
// SpectralNetLoss:
//   2n·loss = Σ_ij W_ij(sq_i + sq_j) − 2 Σ_ij W_ij (y_i·y_j)
// ALL terms via one bf16 mma.sync m16n8k16 GEMM U = W × B̃,
//   B̃ = [Y | sq | 1 | 0…] (72 cols, 9 n8-fragments, rn-bf16):
//   U[:,0..63] folded with Y -> dot;  U[:,64]=(W·sq)_i, U[:,65]=r_i -> term1.
// R16: WARP-PRIVATE pipelines — each warp owns 16 M-rows + a private SMEM
//   slice (its A rows + its own B̃ copy, double-buffered). cp.async waits are
//   per-warp -> ZERO __syncthreads in the main loop (only __syncwarp x2).
//   256 thr x 8 warps, 2 CTAs/SM (16 warps, 224KB smem), KSPLIT=9.
// ============================================================================

#define N_DIM     8192
#define KF        64
#define M_TILE    128
#define KCHUNK    32
#define KSPLIT    9
#define RS        40                        // CF LDS.64 stride (R12-proven)

#define WA_BYTES  (16 * RS * 4)             // 2560: warp's 16 A rows
#define WB_OFF    WA_BYTES
#define B_BYTES   4608                      // 2 kst x 9 nt x 32 lanes x 8B
#define WSTAGE    (WA_BYTES + B_BYTES)      // 7168
#define WTOTAL    (2 * WSTAGE)              // 14336 per warp (double buffer)
#define SMEM_BYTES (8 * WTOTAL)             // 114688 per CTA (x2 = 224KB/SM)

#define NCHUNK    (N_DIM / KCHUNK)          // 256

// B̃ packed per chunk c: [kst][nt][lane] uint2, lane = g*4+q:
//   .x = bf16x2( B̃[k0][n], B̃[k0+1][n] ), .y = bf16x2( B̃[k0+8][n], B̃[k0+9][n] )
//   k0 = c*32 + kst*16 + 2q, n = nt*8+g.  nt=8 -> cols 64..71 = [sq|1|0…].
__device__ float g_Bp[(size_t)NCHUNK * B_BYTES / 4];
__device__ float g_sq[N_DIM];

// ---------------------------------------------------------------- helpers
__device__ __forceinline__ uint32_t smem_u32(const void* p) {
    uint32_t a;
    asm("{ .reg .u64 t; cvta.to.shared.u64 t, %1; cvt.u32.u64 %0, t; }"
        : "=r"(a) : "l"(p));
    return a;
}
__device__ __forceinline__ void cp_async16(uint32_t dst, const void* src) {
    asm volatile("cp.async.cg.shared.global [%0], [%1], 16;"
                 :: "r"(dst), "l"(src));
}
__device__ __forceinline__ void cp_commit() {
    asm volatile("cp.async.commit_group;" ::: "memory");
}
__device__ __forceinline__ void cp_wait1() {
    asm volatile("cp.async.wait_group 1;" ::: "memory");
}
__device__ __forceinline__ uint32_t bf16pair(float lo, float hi) {
    uint32_t r;   // hi -> upper 16 bits, lo -> lower 16 bits
    asm("cvt.rn.bf16x2.f32 %0, %1, %2;" : "=r"(r) : "f"(hi), "f"(lo));
    return r;
}
__device__ __forceinline__ void mma_bf16(float* c, const uint32_t* a,
                                         uint32_t b0, uint32_t b1) {
    asm volatile(
        "mma.sync.aligned.m16n8k16.row.col.f32.bf16.bf16.f32 "
        "{%0,%1,%2,%3}, {%4,%5,%6,%7}, {%8,%9}, {%0,%1,%2,%3};"
        : "+f"(c[0]), "+f"(c[1]), "+f"(c[2]), "+f"(c[3])
        : "r"(a[0]), "r"(a[1]), "r"(a[2]), "r"(a[3]), "r"(b0), "r"(b1));
}

// ---------------------------------------------------------------- fused prep
// Block b handles k-rows [b*32, b*32+32) = chunk b: sq + bf16 B̃ pack.
__global__ void spec_prep(const float* __restrict__ Y, float* __restrict__ out) {
    __shared__ float sY[32 * 72];           // [k][n], stride 72
    __shared__ float ssq[32];
    const int tid = threadIdx.x;
    const int b = blockIdx.x;
    const int k0g = b * 32;

    if (b == 0 && tid == 0) out[0] = 0.0f;

#pragma unroll
    for (int i = 0; i < 8; i++) {
        int idx = tid + i * 256;            // coalesced 32x64 load
        sY[(idx >> 6) * 72 + (idx & 63)] = Y[(size_t)k0g * KF + idx];
    }
    __syncthreads();

    {   // sq: 8 threads per row
        int r = tid >> 3, p = tid & 7;
        const float* row = sY + r * 72 + p * 8;
        float s = 0.0f;
#pragma unroll
        for (int c = 0; c < 8; c++) s += row[c] * row[c];
#pragma unroll
        for (int o = 4; o; o >>= 1) s += __shfl_xor_sync(0xffffffffu, s, o);
        if (p == 0) { ssq[r] = s; g_sq[k0g + r] = s; }
    }
    __syncthreads();

    // pack: 2 kst x 9 nt x 32 lanes = 576 uint2; coalesced 8B writes
#pragma unroll
    for (int i = 0; i < 3; i++) {
        int u = tid + i * 256;              // [kst][nt][lane]
        if (u >= 576) break;
        int lane = u & 31;
        int nt   = (u >> 5) % 9;
        int kst  = u / 288;
        int q = lane & 3, g = lane >> 2;
        int ka = kst * 16 + 2 * q;          // k rel. to chunk
        uint2 v;
        if (nt < 8) {
            int n = nt * 8 + g;
            v.x = bf16pair(sY[ka * 72 + n],       sY[(ka + 1) * 72 + n]);
            v.y = bf16pair(sY[(ka + 8) * 72 + n], sY[(ka + 9) * 72 + n]);
        } else if (g == 0) {                // col 64 = sq_k
            v.x = bf16pair(ssq[ka],     ssq[ka + 1]);
            v.y = bf16pair(ssq[ka + 8], ssq[ka + 9]);
        } else if (g == 1) {                // col 65 = ones
            v.x = bf16pair(1.0f, 1.0f);
            v.y = v.x;
        } else {                            // cols 66..71 = zeros
            v.x = 0u; v.y = 0u;
        }
        *(uint2*)((char*)g_Bp + (size_t)b * B_BYTES + u * 8) = v;
    }
}

// ---------------------------------------------------------------- warp loader
// Loads THIS warp's 16 A rows + its own B̃ copy for one chunk. Per-warp only.
__device__ __forceinline__ void load_chunk_w(uint32_t wdst, const float* wp,
                                             const char* bp, int lane) {
#pragma unroll
    for (int u = 0; u < 4; u++) {
        int idx = lane + u * 32;                      // 16 rows x 8 float4
        int r = idx >> 3, sg = idx & 7;
        cp_async16(wdst + (uint32_t)(r * RS + sg * 4) * 4,
                   wp + (size_t)r * N_DIM + sg * 4);
    }
#pragma unroll
    for (int u = 0; u < 9; u++) {                     // B̃ pack: 288 float4
        int idx = lane + u * 32;
        cp_async16(wdst + WB_OFF + idx * 16, bp + idx * 16);
    }
}

// ---------------------------------------------------------------- main
__global__ void __launch_bounds__(256, 2)
spec_main(const float* __restrict__ W, const float* __restrict__ Y,
          float* __restrict__ out) {
    extern __shared__ float smem[];
    char* smc = (char*)smem;
    const uint32_t sb = smem_u32(smem);

    const int tid  = threadIdx.x;
    const int w    = tid >> 5;         // warp 0..7: rows [w*16, w*16+16)
    const int lane = tid & 31;
    const int q    = lane & 3;
    const int g    = lane >> 2;

    const int bx    = blockIdx.x;
    const int mtile = bx & 63;
    const int ks    = bx >> 6;                              // 0..8
    const int m0    = mtile * M_TILE;
    const int row0  = m0 + w * 16;
    const int c0    = (ks < 4) ? ks * 29 : 116 + (ks - 4) * 28;
    const int nch   = (ks < 4) ? 29 : 28;

    const float* wbase = W + (size_t)row0 * N_DIM + (size_t)c0 * KCHUNK;
    const char*  bbase = (const char*)g_Bp + (size_t)c0 * B_BYTES;
    const uint32_t myS = sb + w * WTOTAL;

    float acc[9][4];                   // frags 0..7 = Y cols; 8 = cols 64..71
#pragma unroll
    for (int nt = 0; nt < 9; nt++)
#pragma unroll
        for (int v = 0; v < 4; v++) acc[nt][v] = 0.0f;

    // prologue: chunks 0,1 in flight (per-warp groups)
    load_chunk_w(myS, wbase, bbase, lane);
    cp_commit();
    if (nch > 1) {
        load_chunk_w(myS + WSTAGE, wbase + KCHUNK, bbase + B_BYTES, lane);
    }
    cp_commit();

    for (int j = 0; j < nch; j++) {
        cp_wait1();                    // chunk j landed (this warp's groups)
        __syncwarp();                  // cross-lane visibility of async stores

        const float* As = (const float*)(smc + w * WTOTAL + (j & 1) * WSTAGE);
        const char*  Bb = smc + w * WTOTAL + (j & 1) * WSTAGE + WB_OFF +
                          lane * 8;

#pragma unroll
        for (int kst = 0; kst < 2; kst++) {
            const int k0 = kst * 16 + 2 * q;
            // A frags: 4 conflict-free LDS.64 (fp32 -> bf16x2)
            const float* ap = As + g * RS + k0;
            float2 p00 = *(const float2*)ap;             // row g,   k +0,+1
            float2 p01 = *(const float2*)(ap + 8);       // row g,   k +8,+9
            float2 p10 = *(const float2*)(ap + 8 * RS);  // row g+8, k +0,+1
            float2 p11 = *(const float2*)(ap + 8 * RS + 8);
            uint32_t a[4];
            a[0] = bf16pair(p00.x, p00.y);
            a[1] = bf16pair(p10.x, p10.y);
            a[2] = bf16pair(p01.x, p01.y);
            a[3] = bf16pair(p11.x, p11.y);
            // B̃ frags: one conflict-free LDS.64 per nt (private copy)
            const char* Bk = Bb + kst * (B_BYTES / 2);
#pragma unroll
            for (int nt = 0; nt < 9; nt++) {
                uint2 bb = *(const uint2*)(Bk + nt * 256);
                mma_bf16(acc[nt], a, bb.x, bb.y);
            }
        }
        __syncwarp();                  // all lanes done reading before refill

        if (j + 2 < nch)               // refill stage (j+2)&1 = stage j&1
            load_chunk_w(myS + (j & 1) * WSTAGE,
                         wbase + (size_t)(j + 2) * KCHUNK,
                         bbase + (size_t)(j + 2) * B_BYTES, lane);
        cp_commit();                   // empty groups keep the count aligned
    }

    // ------------- epilogue: fold U with Y + extra cols, reduce -------------
    const int r0 = row0 + g;
    float sq0 = g_sq[r0], sq1 = g_sq[r0 + 8];

    float dot = 0.0f;
#pragma unroll
    for (int nt = 0; nt < 8; nt++) {
        const int cc = nt * 8 + 2 * q;
        float2 y0 = *(const float2*)(Y + (size_t)r0 * KF + cc);
        float2 y1 = *(const float2*)(Y + (size_t)(r0 + 8) * KF + cc);
        dot += acc[nt][0] * y0.x + acc[nt][1] * y0.y +
               acc[nt][2] * y1.x + acc[nt][3] * y1.y;
    }
    // q==0 lanes: c0 = col64 = (W·sq)_i, c1 = col65 = rowsum r_i
    // (rows g / g+8); q>=1 lanes hold zero columns -> exact 0.
    float extra = acc[8][0] + sq0 * acc[8][1] + acc[8][2] + sq1 * acc[8][3];

    float total = extra - 2.0f * dot;
#pragma unroll
    for (int o = 16; o; o >>= 1)
        total += __shfl_xor_sync(0xffffffffu, total, o);

    __syncthreads();                   // all warps done with their smem slices
    if (lane == 0) smem[w] = total;
    __syncthreads();
    if (tid == 0) {
        float s = 0.0f;
#pragma unroll
        for (int i = 0; i < 8; i++) s += smem[i];
        atomicAdd(out, s * (1.0f / (2.0f * (float)N_DIM)));
    }
}

// ---------------------------------------------------------------- launch
extern "C" void kernel_launch(void* const* d_in, const int* in_sizes, int n_in,
                              void* d_out, int out_size) {
    const float* W = (const float*)d_in[0];
    const float* Y = (const float*)d_in[1];
    float* out = (float*)d_out;

    cudaFuncSetAttribute(spec_main, cudaFuncAttributeMaxDynamicSharedMemorySize,
                         SMEM_BYTES);

    spec_prep<<<NCHUNK, 256>>>(Y, out);
    spec_main<<<64 * KSPLIT, 256, SMEM_BYTES>>>(W, Y, out);
}